// round 1
// baseline (speedup 1.0000x reference)
#include <cuda_runtime.h>
#include <cuda_bf16.h>
#include <cstdint>

#define NU 100000
#define NI 50000
#define NN 150000           // NU + NI
#define NE 1250000
#define DD 64
#define FEAT (NN * DD)      // 9,600,000 floats

// ---------------- scratch (static device globals; no allocation) -------------
__device__ int   g_deg[NN];
__device__ int   g_rowstart[NN + 1];
__device__ int   g_fill[NN];
__device__ float g_dinv[NN];
__device__ int   g_cols[NE];
__device__ float g_norms[NE];
__device__ float g_X[2][FEAT];   // ping-pong feature buffers
__device__ int   g_is64;         // 1 if edge_index is int64, 0 if int32

// ---------------- helpers ----------------------------------------------------
__device__ __forceinline__ int warp_incl_scan(int v) {
    #pragma unroll
    for (int o = 1; o < 32; o <<= 1) {
        int t = __shfl_up_sync(0xffffffffu, v, o);
        if ((threadIdx.x & 31) >= o) v += t;
    }
    return v;
}

__device__ __forceinline__ int load_edge(const int* ei, int pos) {
    // int64 layout: little-endian, value in low word, high word 0
    return g_is64 ? ei[2 * pos] : ei[pos];
}

// ---------------- kernels ----------------------------------------------------
__global__ void detect_dtype_kernel(const unsigned int* e) {
    // If data is int64, every odd 32-bit word of the first 16 values is 0.
    // If int32, odd words are random node ids in [0,150000): P(all 16 zero) ~ 0.
    unsigned int acc = 0;
    #pragma unroll
    for (int i = 0; i < 16; i++) acc |= e[2 * i + 1];
    g_is64 = (acc == 0u) ? 1 : 0;
}

__global__ void zero_deg_kernel() {
    int i = blockIdx.x * blockDim.x + threadIdx.x;
    if (i < NN) g_deg[i] = 0;
}

__global__ void count_kernel(const int* __restrict__ ei) {
    int e = blockIdx.x * blockDim.x + threadIdx.x;
    if (e >= NE) return;
    int r = load_edge(ei, e);
    atomicAdd(&g_deg[r], 1);
}

__global__ void dinv_kernel() {
    int i = blockIdx.x * blockDim.x + threadIdx.x;
    if (i >= NN) return;
    int d = g_deg[i];
    g_dinv[i] = (d > 0) ? rsqrtf((float)d) : 0.0f;
}

// Single-block exclusive scan of g_deg -> g_rowstart / g_fill (150K elements,
// warp-shuffle scan, 2 barriers per 1024-tile).
__global__ void scan_kernel() {
    __shared__ int shW[32];
    __shared__ int shO[32];
    const int lane = threadIdx.x & 31;
    const int wid  = threadIdx.x >> 5;
    int carry = 0;  // maintained identically by all lanes of warp 0

    for (int base = 0; base < NN; base += 1024) {
        int i = base + (int)threadIdx.x;
        int v = (i < NN) ? g_deg[i] : 0;
        int incl = warp_incl_scan(v);
        if (lane == 31) shW[wid] = incl;
        __syncthreads();
        if (wid == 0) {
            int t = shW[lane];
            int ex = warp_incl_scan(t) - t;     // exclusive scan of warp sums
            shO[lane] = ex + carry;
            int tot = __shfl_sync(0xffffffffu, ex + t, 31);
            carry += tot;
        }
        __syncthreads();
        if (i < NN) {
            int excl = incl - v + shO[wid];
            g_rowstart[i] = excl;
            g_fill[i]     = excl;
        }
    }
    if (threadIdx.x == 0) g_rowstart[NN] = carry;  // == NE
}

__global__ void place_kernel(const int* __restrict__ ei) {
    int e = blockIdx.x * blockDim.x + threadIdx.x;
    if (e >= NE) return;
    int r = load_edge(ei, e);
    int c = load_edge(ei, NE + e);
    float n = g_dinv[r] * g_dinv[c];
    int idx = atomicAdd(&g_fill[r], 1);
    g_cols[idx]  = c;
    g_norms[idx] = n;
}

__global__ void init_kernel(const float* __restrict__ user,
                            const float* __restrict__ item,
                            float* __restrict__ out) {
    int i = blockIdx.x * blockDim.x + threadIdx.x;
    if (i >= FEAT) return;
    float v = (i < NU * DD) ? user[i] : item[i - NU * DD];
    g_X[0][i] = v;
    out[i]    = v;   // acc starts as x0
}

// One warp per row. Each lane owns dims [2*lane, 2*lane+1] (float2, coalesced
// 256B row reads). Atomic-free: CSR segment reduction, fused acc into `out`.
__global__ void spmm_kernel(const float* __restrict__ xin,
                            float* __restrict__ xout,
                            float* __restrict__ out) {
    int warp = (blockIdx.x * blockDim.x + threadIdx.x) >> 5;
    int lane = threadIdx.x & 31;
    if (warp >= NN) return;

    int s = g_rowstart[warp];
    int t = g_rowstart[warp + 1];

    float ax = 0.0f, ay = 0.0f;
    for (int e = s; e < t; e++) {
        int   c = __ldg(&g_cols[e]);
        float n = __ldg(&g_norms[e]);
        const float2* p = reinterpret_cast<const float2*>(xin + (size_t)c * DD) + lane;
        float2 v = __ldg(p);
        ax = fmaf(v.x, n, ax);
        ay = fmaf(v.y, n, ay);
    }

    size_t off = (size_t)warp * DD + 2 * (size_t)lane;
    float2* po = reinterpret_cast<float2*>(xout + off - 2 * lane) + lane;
    po->x = ax; po->y = ay;

    float2* pa = reinterpret_cast<float2*>(out + off - 2 * lane) + lane;
    float2 o = *pa;
    o.x += ax; o.y += ay;
    *pa = o;
}

__global__ void scale_kernel(float* __restrict__ out) {
    int i = blockIdx.x * blockDim.x + threadIdx.x;
    if (i < FEAT) out[i] *= 0.25f;
}

// ---------------- launch ------------------------------------------------------
extern "C" void kernel_launch(void* const* d_in, const int* in_sizes, int n_in,
                              void* d_out, int out_size) {
    const float* user = (const float*)d_in[0];
    const float* item = (const float*)d_in[1];
    const int*   ei   = (const int*)d_in[2];   // int32 or int64; detected on device
    float* out = (float*)d_out;

    const int T = 256;
    detect_dtype_kernel<<<1, 1>>>((const unsigned int*)ei);
    zero_deg_kernel<<<(NN + T - 1) / T, T>>>();
    count_kernel<<<(NE + T - 1) / T, T>>>(ei);
    dinv_kernel<<<(NN + T - 1) / T, T>>>();
    scan_kernel<<<1, 1024>>>();
    place_kernel<<<(NE + T - 1) / T, T>>>(ei);
    init_kernel<<<(FEAT + T - 1) / T, T>>>(user, item, out);

    // Resolve symbol addresses host-side (no allocation; just address lookup).
    float* X0 = nullptr; float* X1 = nullptr;
    cudaGetSymbolAddress((void**)&X0, g_X);
    X1 = X0 + FEAT;

    const int spmm_blocks = (NN * 32 + T - 1) / T;   // one warp per row
    spmm_kernel<<<spmm_blocks, T>>>(X0, X1, out);    // x1
    spmm_kernel<<<spmm_blocks, T>>>(X1, X0, out);    // x2
    spmm_kernel<<<spmm_blocks, T>>>(X0, X1, out);    // x3
    scale_kernel<<<(FEAT + T - 1) / T, T>>>(out);
}

// round 6
// speedup vs baseline: 1.4483x; 1.4483x over previous
#include <cuda_runtime.h>
#include <cuda_bf16.h>
#include <cstdint>

#define NU 100000
#define NI 50000
#define NN 150000           // NU + NI
#define NE 1250000
#define DD 64
#define FEAT (NN * DD)      // 9,600,000 floats
#define SCAN_B 1024
#define SCAN_NB ((NN + SCAN_B - 1) / SCAN_B)   // 147

// ---------------- scratch (static device globals; no allocation) -------------
__device__ int   g_deg[NN];
__device__ int   g_rowstart[NN + 1];
__device__ int   g_fill[NN];
__device__ float g_dinv[NN];
__device__ int2  g_edge[NE];        // {col, __float_as_int(norm)}
__device__ int   g_bsum[SCAN_NB];
__device__ int   g_bofs[SCAN_NB];
__device__ float g_X[2][FEAT];      // ping-pong feature buffers (x1, x2)
__device__ int   g_is64;            // 1 if edge_index is int64, 0 if int32

// ---------------- helpers ----------------------------------------------------
__device__ __forceinline__ int warp_incl_scan(int v) {
    #pragma unroll
    for (int o = 1; o < 32; o <<= 1) {
        int t = __shfl_up_sync(0xffffffffu, v, o);
        if ((threadIdx.x & 31) >= o) v += t;
    }
    return v;
}

__device__ __forceinline__ int load_edge(const int* ei, int pos) {
    return g_is64 ? ei[2 * pos] : ei[pos];
}

// ---------------- preprocessing kernels --------------------------------------
__global__ void detect_dtype_kernel(const unsigned int* e) {
    unsigned int acc = 0;
    #pragma unroll
    for (int i = 0; i < 16; i++) acc |= e[2 * i + 1];
    g_is64 = (acc == 0u) ? 1 : 0;
}

__global__ void zero_deg_kernel() {
    int i = blockIdx.x * blockDim.x + threadIdx.x;
    if (i < NN) g_deg[i] = 0;
}

__global__ void count_kernel(const int* __restrict__ ei) {
    int e = blockIdx.x * blockDim.x + threadIdx.x;
    if (e >= NE) return;
    atomicAdd(&g_deg[load_edge(ei, e)], 1);
}

__global__ void dinv_kernel() {
    int i = blockIdx.x * blockDim.x + threadIdx.x;
    if (i >= NN) return;
    int d = g_deg[i];
    g_dinv[i] = (d > 0) ? rsqrtf((float)d) : 0.0f;
}

// -------- 3-phase parallel scan of g_deg -> g_rowstart / g_fill ---------------
__global__ void scan1_kernel() {            // per-block sums
    __shared__ int shW[32];
    int i = blockIdx.x * SCAN_B + threadIdx.x;
    int v = (i < NN) ? g_deg[i] : 0;
    int incl = warp_incl_scan(v);
    if ((threadIdx.x & 31) == 31) shW[threadIdx.x >> 5] = incl;
    __syncthreads();
    if (threadIdx.x < 32) {
        int t = (threadIdx.x < SCAN_B / 32) ? shW[threadIdx.x] : 0;
        int s = warp_incl_scan(t);
        if (threadIdx.x == SCAN_B / 32 - 1) g_bsum[blockIdx.x] = s;
    }
}

__global__ void scan2_kernel() {            // exclusive scan of 147 block sums
    __shared__ int sh[256];
    int t = threadIdx.x;
    sh[t] = (t < SCAN_NB) ? g_bsum[t] : 0;
    __syncthreads();
    #pragma unroll
    for (int o = 1; o < 256; o <<= 1) {
        int v = (t >= o) ? sh[t - o] : 0;
        __syncthreads();
        sh[t] += v;
        __syncthreads();
    }
    if (t < SCAN_NB) g_bofs[t] = sh[t] - g_bsum[t];   // exclusive
}

__global__ void scan3_kernel() {            // local scan + block offset
    __shared__ int shW[32];
    __shared__ int shO[32];
    const int lane = threadIdx.x & 31;
    const int wid  = threadIdx.x >> 5;
    int i = blockIdx.x * SCAN_B + threadIdx.x;
    int v = (i < NN) ? g_deg[i] : 0;
    int incl = warp_incl_scan(v);
    if (lane == 31) shW[wid] = incl;
    __syncthreads();
    if (wid == 0) {
        int t = (lane < SCAN_B / 32) ? shW[lane] : 0;
        shO[lane] = warp_incl_scan(t) - t;
    }
    __syncthreads();
    if (i < NN) {
        int excl = incl - v + shO[wid] + g_bofs[blockIdx.x];
        g_rowstart[i] = excl;
        g_fill[i]     = excl;
    }
    if (blockIdx.x == 0 && threadIdx.x == 0) g_rowstart[NN] = NE;
}

__global__ void place_kernel(const int* __restrict__ ei) {
    int e = blockIdx.x * blockDim.x + threadIdx.x;
    if (e >= NE) return;
    int r = load_edge(ei, e);
    int c = load_edge(ei, NE + e);
    float n = g_dinv[r] * g_dinv[c];
    int idx = atomicAdd(&g_fill[r], 1);
    g_edge[idx] = make_int2(c, __float_as_int(n));
}

// ---------------- SpMM --------------------------------------------------------
// One warp per row; lane owns dims [2*lane, 2*lane+1] (float2, coalesced 256B).
// MODE 0: gather from split user/item inputs; out = x0_row + x1; xout = x1
// MODE 1: gather from xin;                    out += x2;         xout = x2
// MODE 2: gather from xin;                    out = (out+x3)/4;  no xout
template <int MODE>
__global__ void spmm_kernel(const float* __restrict__ user,
                            const float* __restrict__ item,
                            const float* __restrict__ xin,
                            float* __restrict__ xout,
                            float* __restrict__ out) {
    int row  = (blockIdx.x * blockDim.x + threadIdx.x) >> 5;
    int lane = threadIdx.x & 31;
    if (row >= NN) return;

    int s = g_rowstart[row];
    int t = g_rowstart[row + 1];

    float ax = 0.0f, ay = 0.0f, bx = 0.0f, by = 0.0f;
    int e = s;
    for (; e + 1 < t; e += 2) {
        int2 e0 = __ldg(&g_edge[e]);
        int2 e1 = __ldg(&g_edge[e + 1]);
        const float2 *p0, *p1;
        if (MODE == 0) {
            const float* b0 = (e0.x < NU) ? user + (size_t)e0.x * DD
                                          : item + (size_t)(e0.x - NU) * DD;
            const float* b1 = (e1.x < NU) ? user + (size_t)e1.x * DD
                                          : item + (size_t)(e1.x - NU) * DD;
            p0 = reinterpret_cast<const float2*>(b0) + lane;
            p1 = reinterpret_cast<const float2*>(b1) + lane;
        } else {
            p0 = reinterpret_cast<const float2*>(xin + (size_t)e0.x * DD) + lane;
            p1 = reinterpret_cast<const float2*>(xin + (size_t)e1.x * DD) + lane;
        }
        float2 v0 = __ldg(p0);
        float2 v1 = __ldg(p1);
        float n0 = __int_as_float(e0.y);
        float n1 = __int_as_float(e1.y);
        ax = fmaf(v0.x, n0, ax);  ay = fmaf(v0.y, n0, ay);
        bx = fmaf(v1.x, n1, bx);  by = fmaf(v1.y, n1, by);
    }
    if (e < t) {
        int2 e0 = __ldg(&g_edge[e]);
        const float2* p0;
        if (MODE == 0) {
            const float* b0 = (e0.x < NU) ? user + (size_t)e0.x * DD
                                          : item + (size_t)(e0.x - NU) * DD;
            p0 = reinterpret_cast<const float2*>(b0) + lane;
        } else {
            p0 = reinterpret_cast<const float2*>(xin + (size_t)e0.x * DD) + lane;
        }
        float2 v0 = __ldg(p0);
        float n0 = __int_as_float(e0.y);
        ax = fmaf(v0.x, n0, ax);  ay = fmaf(v0.y, n0, ay);
    }
    ax += bx;  ay += by;

    size_t base = (size_t)row * DD;
    if (MODE != 2) {
        float2* po = reinterpret_cast<float2*>(xout + base) + lane;
        po->x = ax;  po->y = ay;
    }

    float2* pa = reinterpret_cast<float2*>(out + base) + lane;
    if (MODE == 0) {
        // out = x0_row + x1 ; x0_row comes from the split inputs
        const float* xb = (row < NU) ? user + base : item + (base - (size_t)NU * DD);
        float2 x0 = __ldg(reinterpret_cast<const float2*>(xb) + lane);
        pa->x = x0.x + ax;  pa->y = x0.y + ay;
    } else if (MODE == 1) {
        float2 o = *pa;
        pa->x = o.x + ax;  pa->y = o.y + ay;
    } else {
        float2 o = *pa;
        pa->x = (o.x + ax) * 0.25f;  pa->y = (o.y + ay) * 0.25f;
    }
}

// ---------------- launch ------------------------------------------------------
extern "C" void kernel_launch(void* const* d_in, const int* in_sizes, int n_in,
                              void* d_out, int out_size) {
    const float* user = (const float*)d_in[0];
    const float* item = (const float*)d_in[1];
    const int*   ei   = (const int*)d_in[2];   // int32 or int64; device-detected
    float* out = (float*)d_out;

    const int T = 256;
    detect_dtype_kernel<<<1, 1>>>((const unsigned int*)ei);
    zero_deg_kernel<<<(NN + T - 1) / T, T>>>();
    count_kernel<<<(NE + T - 1) / T, T>>>(ei);
    dinv_kernel<<<(NN + T - 1) / T, T>>>();
    scan1_kernel<<<SCAN_NB, SCAN_B>>>();
    scan2_kernel<<<1, 256>>>();
    scan3_kernel<<<SCAN_NB, SCAN_B>>>();
    place_kernel<<<(NE + T - 1) / T, T>>>(ei);

    float* X0 = nullptr;
    cudaGetSymbolAddress((void**)&X0, g_X);
    float* X1 = X0 + FEAT;

    const int spmm_blocks = (NN * 32 + T - 1) / T;   // one warp per row
    spmm_kernel<0><<<spmm_blocks, T>>>(user, item, nullptr, X0, out);  // x1
    spmm_kernel<1><<<spmm_blocks, T>>>(user, item, X0, X1, out);       // x2
    spmm_kernel<2><<<spmm_blocks, T>>>(user, item, X1, nullptr, out);  // x3 + /4
}

// round 7
// speedup vs baseline: 1.8347x; 1.2668x over previous
#include <cuda_runtime.h>
#include <cuda_fp16.h>
#include <cstdint>

#define NU 100000
#define NI 50000
#define NN 150000           // NU + NI
#define NE 1250000
#define DD 64
#define FEAT (NN * DD)      // 9,600,000 floats
#define FEATH (FEAT / 2)    // half2 elements
#define SCAN_B 1024
#define SCAN_NB ((NN + SCAN_B - 1) / SCAN_B)   // 147

// ---------------- scratch (static device globals; no allocation) -------------
__device__ int     g_deg[NN];
__device__ int     g_rowstart[NN + 1];
__device__ int     g_fill[NN];
__device__ float   g_dinv[NN];
__device__ int2    g_edge[NE];        // {col, __float_as_int(norm)}
__device__ int     g_bsum[SCAN_NB];
__device__ int     g_bofs[SCAN_NB];
__device__ __half2 g_Xh[3][FEATH];    // fp16 feature buffers: x0, x1, x2
__device__ int     g_is64;            // 1 if edge_index is int64, 0 if int32

// ---------------- helpers ----------------------------------------------------
__device__ __forceinline__ int warp_incl_scan(int v) {
    #pragma unroll
    for (int o = 1; o < 32; o <<= 1) {
        int t = __shfl_up_sync(0xffffffffu, v, o);
        if ((threadIdx.x & 31) >= o) v += t;
    }
    return v;
}

__device__ __forceinline__ int load_edge(const int* ei, int pos) {
    return g_is64 ? ei[2 * pos] : ei[pos];
}

// ---------------- preprocessing kernels --------------------------------------
// Fused: zero g_deg + dtype detection (thread 0 only).
__global__ void zero_detect_kernel(const unsigned int* e) {
    int i = blockIdx.x * blockDim.x + threadIdx.x;
    if (i < NN) g_deg[i] = 0;
    if (i == 0) {
        // int64 => odd 32-bit words of first 16 values are all zero.
        unsigned int acc = 0;
        #pragma unroll
        for (int k = 0; k < 16; k++) acc |= e[2 * k + 1];
        g_is64 = (acc == 0u) ? 1 : 0;
    }
}

__global__ void count_kernel(const int* __restrict__ ei) {
    int e = blockIdx.x * blockDim.x + threadIdx.x;
    if (e >= NE) return;
    atomicAdd(&g_deg[load_edge(ei, e)], 1);
}

// Fused: per-block scan sums + dinv computation.
__global__ void scan1_dinv_kernel() {
    __shared__ int shW[32];
    int i = blockIdx.x * SCAN_B + threadIdx.x;
    int v = 0;
    if (i < NN) {
        v = g_deg[i];
        g_dinv[i] = (v > 0) ? rsqrtf((float)v) : 0.0f;
    }
    int incl = warp_incl_scan(v);
    if ((threadIdx.x & 31) == 31) shW[threadIdx.x >> 5] = incl;
    __syncthreads();
    if (threadIdx.x < 32) {
        int t = (threadIdx.x < SCAN_B / 32) ? shW[threadIdx.x] : 0;
        int s = warp_incl_scan(t);
        if (threadIdx.x == SCAN_B / 32 - 1) g_bsum[blockIdx.x] = s;
    }
}

__global__ void scan2_kernel() {            // exclusive scan of 147 block sums
    __shared__ int sh[256];
    int t = threadIdx.x;
    sh[t] = (t < SCAN_NB) ? g_bsum[t] : 0;
    __syncthreads();
    #pragma unroll
    for (int o = 1; o < 256; o <<= 1) {
        int v = (t >= o) ? sh[t - o] : 0;
        __syncthreads();
        sh[t] += v;
        __syncthreads();
    }
    if (t < SCAN_NB) g_bofs[t] = sh[t] - g_bsum[t];   // exclusive
}

__global__ void scan3_kernel() {            // local scan + block offset
    __shared__ int shW[32];
    __shared__ int shO[32];
    const int lane = threadIdx.x & 31;
    const int wid  = threadIdx.x >> 5;
    int i = blockIdx.x * SCAN_B + threadIdx.x;
    int v = (i < NN) ? g_deg[i] : 0;
    int incl = warp_incl_scan(v);
    if (lane == 31) shW[wid] = incl;
    __syncthreads();
    if (wid == 0) {
        int t = (lane < SCAN_B / 32) ? shW[lane] : 0;
        shO[lane] = warp_incl_scan(t) - t;
    }
    __syncthreads();
    if (i < NN) {
        int excl = incl - v + shO[wid] + g_bofs[blockIdx.x];
        g_rowstart[i] = excl;
        g_fill[i]     = excl;
    }
    if (blockIdx.x == 0 && threadIdx.x == 0) g_rowstart[NN] = NE;
}

__global__ void place_kernel(const int* __restrict__ ei) {
    int e = blockIdx.x * blockDim.x + threadIdx.x;
    if (e >= NE) return;
    int r = load_edge(ei, e);
    int c = load_edge(ei, NE + e);
    float n = g_dinv[r] * g_dinv[c];
    int idx = atomicAdd(&g_fill[r], 1);
    g_edge[idx] = make_int2(c, __float_as_int(n));
}

// Convert fp32 inputs -> fp16 x0 buffer (gather source for layer 1).
__global__ void convert_kernel(const float* __restrict__ user,
                               const float* __restrict__ item) {
    int i = blockIdx.x * blockDim.x + threadIdx.x;   // half2 index
    if (i >= FEATH) return;
    int j = 2 * i;                                   // NU*DD is even: no straddle
    float2 v;
    if (j < NU * DD) v = *reinterpret_cast<const float2*>(user + j);
    else             v = *reinterpret_cast<const float2*>(item + (j - NU * DD));
    g_Xh[0][i] = __floats2half2_rn(v.x, v.y);
}

// ---------------- SpMM --------------------------------------------------------
// One warp per row; lane owns dims [2*lane, 2*lane+1] via one half2 (4B/lane,
// 128B/row coalesced). fp32 accumulation; gathered operand is fp16.
// MODE 0: out = x0_row + x1 (x0 from fp32 inputs); xout = x1 (fp16)
// MODE 1: out += x2;                               xout = x2 (fp16)
// MODE 2: out = (out + x3) * 0.25;                 no xout
template <int MODE>
__global__ void spmm_kernel(const float* __restrict__ user,
                            const float* __restrict__ item,
                            const __half2* __restrict__ xin,
                            __half2* __restrict__ xout,
                            float* __restrict__ out) {
    int row  = (blockIdx.x * blockDim.x + threadIdx.x) >> 5;
    int lane = threadIdx.x & 31;
    if (row >= NN) return;

    int s = g_rowstart[row];
    int t = g_rowstart[row + 1];

    float ax = 0.0f, ay = 0.0f, bx = 0.0f, by = 0.0f;
    int e = s;
    for (; e + 1 < t; e += 2) {
        int2 e0 = __ldg(&g_edge[e]);
        int2 e1 = __ldg(&g_edge[e + 1]);
        float2 v0 = __half22float2(__ldg(xin + (size_t)e0.x * (DD / 2) + lane));
        float2 v1 = __half22float2(__ldg(xin + (size_t)e1.x * (DD / 2) + lane));
        float n0 = __int_as_float(e0.y);
        float n1 = __int_as_float(e1.y);
        ax = fmaf(v0.x, n0, ax);  ay = fmaf(v0.y, n0, ay);
        bx = fmaf(v1.x, n1, bx);  by = fmaf(v1.y, n1, by);
    }
    if (e < t) {
        int2 e0 = __ldg(&g_edge[e]);
        float2 v0 = __half22float2(__ldg(xin + (size_t)e0.x * (DD / 2) + lane));
        float n0 = __int_as_float(e0.y);
        ax = fmaf(v0.x, n0, ax);  ay = fmaf(v0.y, n0, ay);
    }
    ax += bx;  ay += by;

    size_t base = (size_t)row * DD;
    if (MODE != 2) {
        xout[(size_t)row * (DD / 2) + lane] = __floats2half2_rn(ax, ay);
    }

    float2* pa = reinterpret_cast<float2*>(out + base) + lane;
    if (MODE == 0) {
        // out = x0_row + x1 ; x0_row read at full fp32 precision from inputs
        const float* xb = (row < NU) ? user + base : item + (base - (size_t)NU * DD);
        float2 x0 = __ldg(reinterpret_cast<const float2*>(xb) + lane);
        pa->x = x0.x + ax;  pa->y = x0.y + ay;
    } else if (MODE == 1) {
        float2 o = *pa;
        pa->x = o.x + ax;  pa->y = o.y + ay;
    } else {
        float2 o = *pa;
        pa->x = (o.x + ax) * 0.25f;  pa->y = (o.y + ay) * 0.25f;
    }
}

// ---------------- launch ------------------------------------------------------
extern "C" void kernel_launch(void* const* d_in, const int* in_sizes, int n_in,
                              void* d_out, int out_size) {
    const float* user = (const float*)d_in[0];
    const float* item = (const float*)d_in[1];
    const int*   ei   = (const int*)d_in[2];   // int32 or int64; device-detected
    float* out = (float*)d_out;

    const int T = 256;
    zero_detect_kernel<<<(NN + T - 1) / T, T>>>((const unsigned int*)ei);
    count_kernel<<<(NE + T - 1) / T, T>>>(ei);
    scan1_dinv_kernel<<<SCAN_NB, SCAN_B>>>();
    scan2_kernel<<<1, 256>>>();
    scan3_kernel<<<SCAN_NB, SCAN_B>>>();
    place_kernel<<<(NE + T - 1) / T, T>>>(ei);
    convert_kernel<<<(FEATH + T - 1) / T, T>>>(user, item);

    __half2* X0 = nullptr;
    cudaGetSymbolAddress((void**)&X0, g_Xh);
    __half2* X1 = X0 + FEATH;
    __half2* X2 = X1 + FEATH;

    const int spmm_blocks = (NN * 32 + T - 1) / T;   // one warp per row
    spmm_kernel<0><<<spmm_blocks, T>>>(user, item, X0, X1, out);      // x1
    spmm_kernel<1><<<spmm_blocks, T>>>(user, item, X1, X2, out);      // x2
    spmm_kernel<2><<<spmm_blocks, T>>>(user, item, X2, nullptr, out); // x3 + /4
}

// round 10
// speedup vs baseline: 2.0847x; 1.1362x over previous
#include <cuda_runtime.h>
#include <cuda_fp16.h>
#include <cstdint>

#define NU 100000
#define NI 50000
#define NN 150000           // NU + NI (even)
#define NE 1250000
#define DD 64
#define FEAT (NN * DD)      // 9,600,000 floats
#define FEATH (FEAT / 2)    // half2 elements
#define SCAN_B 1024
#define SCAN_NB ((NN + SCAN_B - 1) / SCAN_B)   // 147

// ---------------- scratch (static device globals; no allocation) -------------
__device__ int     g_deg[NN];
__device__ int     g_rowstart[NN + 1];
__device__ int     g_fill[NN];
__device__ float   g_dinv[NN];
__device__ int2    g_edge[NE];        // {col, __float_as_int(norm)}
__device__ int     g_bsum[SCAN_NB];
__device__ __half2 g_Xh[3][FEATH];    // fp16 feature buffers: x0, x1, x2
__device__ int     g_is64;

// ---------------- helpers ----------------------------------------------------
__device__ __forceinline__ int warp_incl_scan(int v) {
    #pragma unroll
    for (int o = 1; o < 32; o <<= 1) {
        int t = __shfl_up_sync(0xffffffffu, v, o);
        if ((threadIdx.x & 31) >= o) v += t;
    }
    return v;
}

__device__ __forceinline__ int load_edge(const int* ei, int pos) {
    return g_is64 ? ei[2 * pos] : ei[pos];
}

// ---------------- preprocessing kernels --------------------------------------
__global__ void zero_detect_kernel(const unsigned int* e) {
    int i = blockIdx.x * blockDim.x + threadIdx.x;
    if (i < NN) g_deg[i] = 0;
    if (i == 0) {
        unsigned int acc = 0;
        #pragma unroll
        for (int k = 0; k < 16; k++) acc |= e[2 * k + 1];
        g_is64 = (acc == 0u) ? 1 : 0;
    }
}

__global__ void count_kernel(const int* __restrict__ ei) {
    int e = blockIdx.x * blockDim.x + threadIdx.x;
    if (e >= NE) return;
    atomicAdd(&g_deg[load_edge(ei, e)], 1);
}

// Fused: per-block scan sums + dinv computation.
__global__ void scan1_dinv_kernel() {
    __shared__ int shW[32];
    int i = blockIdx.x * SCAN_B + threadIdx.x;
    int v = 0;
    if (i < NN) {
        v = g_deg[i];
        g_dinv[i] = (v > 0) ? rsqrtf((float)v) : 0.0f;
    }
    int incl = warp_incl_scan(v);
    if ((threadIdx.x & 31) == 31) shW[threadIdx.x >> 5] = incl;
    __syncthreads();
    if (threadIdx.x < 32) {
        int t = (threadIdx.x < SCAN_B / 32) ? shW[threadIdx.x] : 0;
        int s = warp_incl_scan(t);
        if (threadIdx.x == SCAN_B / 32 - 1) g_bsum[blockIdx.x] = s;
    }
}

// Fused: each block redundantly scans the 147 block sums (cheap), then does
// its local scan + offset. Replaces the old separate scan2 launch.
__global__ void scan3_kernel() {
    __shared__ int shB[256];
    __shared__ int shW[32];
    __shared__ int shO[32];
    __shared__ int s_bofs;
    const int tid  = threadIdx.x;
    const int lane = tid & 31;
    const int wid  = tid >> 5;

    if (tid < 256) shB[tid] = (tid < SCAN_NB) ? g_bsum[tid] : 0;
    __syncthreads();
    #pragma unroll
    for (int o = 1; o < 256; o <<= 1) {
        int v = (tid < 256 && tid >= o) ? shB[tid - o] : 0;
        __syncthreads();
        if (tid < 256) shB[tid] += v;
        __syncthreads();
    }
    if (tid == 0) s_bofs = (blockIdx.x > 0) ? shB[blockIdx.x - 1] : 0;
    __syncthreads();

    int i = blockIdx.x * SCAN_B + tid;
    int v = (i < NN) ? g_deg[i] : 0;
    int incl = warp_incl_scan(v);
    if (lane == 31) shW[wid] = incl;
    __syncthreads();
    if (wid == 0) {
        int t = (lane < SCAN_B / 32) ? shW[lane] : 0;
        shO[lane] = warp_incl_scan(t) - t;
    }
    __syncthreads();
    if (i < NN) {
        int excl = incl - v + shO[wid] + s_bofs;
        g_rowstart[i] = excl;
        g_fill[i]     = excl;
    }
    if (blockIdx.x == 0 && tid == 0) g_rowstart[NN] = NE;
}

__global__ void place_kernel(const int* __restrict__ ei) {
    int e = blockIdx.x * blockDim.x + threadIdx.x;
    if (e >= NE) return;
    int r = load_edge(ei, e);
    int c = load_edge(ei, NE + e);
    float n = g_dinv[r] * g_dinv[c];
    int idx = atomicAdd(&g_fill[r], 1);
    g_edge[idx] = make_int2(c, __float_as_int(n));
}

// Convert fp32 inputs -> fp16 x0 buffer (gather source for layer 1).
__global__ void convert_kernel(const float* __restrict__ user,
                               const float* __restrict__ item) {
    int i = blockIdx.x * blockDim.x + threadIdx.x;   // half2 index
    if (i >= FEATH) return;
    int j = 2 * i;
    float2 v;
    if (j < NU * DD) v = *reinterpret_cast<const float2*>(user + j);
    else             v = *reinterpret_cast<const float2*>(item + (j - NU * DD));
    g_Xh[0][i] = __floats2half2_rn(v.x, v.y);
}

// ---------------- SpMM: 2 rows per warp, 8B lanes ----------------------------
// Lanes 0-15 serve row 2w, lanes 16-31 serve row 2w+1. Each lane owns dims
// [4*sub, 4*sub+4) as one uint2 (2x half2): one LDG.64 gather covers 2 edges
// per warp instruction. fp32 accumulation throughout.
// MODE 0/1: xout = result (fp16). MODE 2: out = (x0 + x1 + x2 + result)*0.25.
template <int MODE>
__global__ void spmm2_kernel(const float* __restrict__ user,
                             const float* __restrict__ item,
                             const __half2* __restrict__ xin,
                             __half2* __restrict__ xout,
                             const __half2* __restrict__ xb1,
                             const __half2* __restrict__ xb2,
                             float* __restrict__ out) {
    int gw   = (blockIdx.x * blockDim.x + threadIdx.x) >> 5;  // warp -> rows 2gw, 2gw+1
    int lane = threadIdx.x & 31;
    if (2 * gw >= NN) return;
    int half = lane >> 4;
    int sub  = lane & 15;
    int row  = 2 * gw + half;

    int s = g_rowstart[row];
    int d = g_rowstart[row + 1] - s;
    int dmax = max(d, __shfl_xor_sync(0xffffffffu, d, 16));

    float a0 = 0, a1 = 0, a2 = 0, a3 = 0;
    float b0 = 0, b1 = 0, b2 = 0, b3 = 0;
    const char* xinb = reinterpret_cast<const char*>(xin);

    for (int i = 0; i < dmax; i += 2) {
        if (i < d) {
            int2 e = __ldg(&g_edge[s + i]);
            uint2 v = __ldg(reinterpret_cast<const uint2*>(xinb + (size_t)e.x * 128) + sub);
            float2 f0 = __half22float2(*reinterpret_cast<__half2*>(&v.x));
            float2 f1 = __half22float2(*reinterpret_cast<__half2*>(&v.y));
            float n = __int_as_float(e.y);
            a0 = fmaf(f0.x, n, a0);  a1 = fmaf(f0.y, n, a1);
            a2 = fmaf(f1.x, n, a2);  a3 = fmaf(f1.y, n, a3);
        }
        if (i + 1 < d) {
            int2 e = __ldg(&g_edge[s + i + 1]);
            uint2 v = __ldg(reinterpret_cast<const uint2*>(xinb + (size_t)e.x * 128) + sub);
            float2 f0 = __half22float2(*reinterpret_cast<__half2*>(&v.x));
            float2 f1 = __half22float2(*reinterpret_cast<__half2*>(&v.y));
            float n = __int_as_float(e.y);
            b0 = fmaf(f0.x, n, b0);  b1 = fmaf(f0.y, n, b1);
            b2 = fmaf(f1.x, n, b2);  b3 = fmaf(f1.y, n, b3);
        }
    }
    a0 += b0;  a1 += b1;  a2 += b2;  a3 += b3;

    if (MODE != 2) {
        __half2 h0 = __floats2half2_rn(a0, a1);
        __half2 h1 = __floats2half2_rn(a2, a3);
        uint2 w;
        w.x = *reinterpret_cast<unsigned int*>(&h0);
        w.y = *reinterpret_cast<unsigned int*>(&h1);
        *(reinterpret_cast<uint2*>(reinterpret_cast<char*>(xout) + (size_t)row * 128) + sub) = w;
    } else {
        size_t base = (size_t)row * DD + 4 * (size_t)sub;
        const float* xb = (row < NU) ? user + base : item + (base - (size_t)NU * DD);
        float4 x0 = __ldg(reinterpret_cast<const float4*>(xb));
        uint2 u1 = __ldg(reinterpret_cast<const uint2*>(
                       reinterpret_cast<const char*>(xb1) + (size_t)row * 128) + sub);
        uint2 u2 = __ldg(reinterpret_cast<const uint2*>(
                       reinterpret_cast<const char*>(xb2) + (size_t)row * 128) + sub);
        float2 p0 = __half22float2(*reinterpret_cast<__half2*>(&u1.x));
        float2 p1 = __half22float2(*reinterpret_cast<__half2*>(&u1.y));
        float2 q0 = __half22float2(*reinterpret_cast<__half2*>(&u2.x));
        float2 q1 = __half22float2(*reinterpret_cast<__half2*>(&u2.y));
        float4 r;
        r.x = (x0.x + p0.x + q0.x + a0) * 0.25f;
        r.y = (x0.y + p0.y + q0.y + a1) * 0.25f;
        r.z = (x0.z + p1.x + q1.x + a2) * 0.25f;
        r.w = (x0.w + p1.y + q1.y + a3) * 0.25f;
        *reinterpret_cast<float4*>(out + base) = r;
    }
}

// ---------------- launch ------------------------------------------------------
extern "C" void kernel_launch(void* const* d_in, const int* in_sizes, int n_in,
                              void* d_out, int out_size) {
    const float* user = (const float*)d_in[0];
    const float* item = (const float*)d_in[1];
    const int*   ei   = (const int*)d_in[2];
    float* out = (float*)d_out;

    const int T = 256;
    zero_detect_kernel<<<(NN + T - 1) / T, T>>>((const unsigned int*)ei);
    count_kernel<<<(NE + T - 1) / T, T>>>(ei);
    scan1_dinv_kernel<<<SCAN_NB, SCAN_B>>>();
    scan3_kernel<<<SCAN_NB, SCAN_B>>>();
    place_kernel<<<(NE + T - 1) / T, T>>>(ei);
    convert_kernel<<<(FEATH + T - 1) / T, T>>>(user, item);

    __half2* X0 = nullptr;
    cudaGetSymbolAddress((void**)&X0, g_Xh);
    __half2* X1 = X0 + FEATH;
    __half2* X2 = X1 + FEATH;

    const int warps = NN / 2;                          // 2 rows per warp
    const int spmm_blocks = (warps * 32 + T - 1) / T;  // 9375
    spmm2_kernel<0><<<spmm_blocks, T>>>(user, item, X0, X1, nullptr, nullptr, out);
    spmm2_kernel<1><<<spmm_blocks, T>>>(user, item, X1, X2, nullptr, nullptr, out);
    spmm2_kernel<2><<<spmm_blocks, T>>>(user, item, X2, nullptr, X1, X2, out);
}

// round 16
// speedup vs baseline: 2.6895x; 1.2901x over previous
#include <cuda_runtime.h>
#include <cuda_fp16.h>
#include <cstdint>

#define NU 100000
#define NI 50000
#define NN 150000           // NU + NI (divisible by 4)
#define NE 1250000
#define DD 64
#define FEAT (NN * DD)      // 9,600,000 floats
#define FEATH (FEAT / 2)    // half2 elements
#define SCAN_B 1024
#define SCAN_NB ((NN + SCAN_B - 1) / SCAN_B)   // 147
#define ZERO_BLKS ((NN + 255) / 256)           // 586
#define CONV_BLKS ((FEATH + 255) / 256)        // 18750

// ---------------- scratch (static device globals; no allocation) -------------
__device__ int     g_deg[NN];
__device__ int     g_rowstart[NN + 1];
__device__ int     g_fill[NN];
__device__ float   g_dinv[NN];
__device__ int2    g_edge[NE];        // {col, __float_as_int(norm)}
__device__ int     g_bsum[SCAN_NB];
__device__ __half2 g_Xh[3][FEATH];    // fp16 feature buffers: x0, x1, x2
__device__ int     g_is64;

// ---------------- helpers ----------------------------------------------------
__device__ __forceinline__ int warp_incl_scan(int v) {
    #pragma unroll
    for (int o = 1; o < 32; o <<= 1) {
        int t = __shfl_up_sync(0xffffffffu, v, o);
        if ((threadIdx.x & 31) >= o) v += t;
    }
    return v;
}

__device__ __forceinline__ int load_edge(const int* ei, int pos) {
    return g_is64 ? ei[2 * pos] : ei[pos];
}

__device__ __forceinline__ void unpack8(const uint4& v, float* f) {
    float2 t;
    t = __half22float2(*reinterpret_cast<const __half2*>(&v.x)); f[0] = t.x; f[1] = t.y;
    t = __half22float2(*reinterpret_cast<const __half2*>(&v.y)); f[2] = t.x; f[3] = t.y;
    t = __half22float2(*reinterpret_cast<const __half2*>(&v.z)); f[4] = t.x; f[5] = t.y;
    t = __half22float2(*reinterpret_cast<const __half2*>(&v.w)); f[6] = t.x; f[7] = t.y;
}

// ---------------- preprocessing kernels --------------------------------------
// Fused: zero g_deg + dtype detect + fp32->fp16 convert of x0 (independent work,
// split grid). Blocks [0, ZERO_BLKS) zero deg; blocks [ZERO_BLKS, ...) convert.
__global__ void zero_detect_convert_kernel(const unsigned int* e,
                                           const float* __restrict__ user,
                                           const float* __restrict__ item) {
    if (blockIdx.x < ZERO_BLKS) {
        int i = blockIdx.x * blockDim.x + threadIdx.x;
        if (i < NN) g_deg[i] = 0;
        if (i == 0) {
            unsigned int acc = 0;
            #pragma unroll
            for (int k = 0; k < 16; k++) acc |= e[2 * k + 1];
            g_is64 = (acc == 0u) ? 1 : 0;
        }
    } else {
        int i = (blockIdx.x - ZERO_BLKS) * blockDim.x + threadIdx.x;  // half2 idx
        if (i >= FEATH) return;
        int j = 2 * i;
        float2 v;
        if (j < NU * DD) v = *reinterpret_cast<const float2*>(user + j);
        else             v = *reinterpret_cast<const float2*>(item + (j - NU * DD));
        g_Xh[0][i] = __floats2half2_rn(v.x, v.y);
    }
}

__global__ void count_kernel(const int* __restrict__ ei) {
    int e = blockIdx.x * blockDim.x + threadIdx.x;
    if (e >= NE) return;
    atomicAdd(&g_deg[load_edge(ei, e)], 1);
}

// Fused: per-block scan sums + dinv computation.
__global__ void scan1_dinv_kernel() {
    __shared__ int shW[32];
    int i = blockIdx.x * SCAN_B + threadIdx.x;
    int v = 0;
    if (i < NN) {
        v = g_deg[i];
        g_dinv[i] = (v > 0) ? rsqrtf((float)v) : 0.0f;
    }
    int incl = warp_incl_scan(v);
    if ((threadIdx.x & 31) == 31) shW[threadIdx.x >> 5] = incl;
    __syncthreads();
    if (threadIdx.x < 32) {
        int t = (threadIdx.x < SCAN_B / 32) ? shW[threadIdx.x] : 0;
        int s = warp_incl_scan(t);
        if (threadIdx.x == SCAN_B / 32 - 1) g_bsum[blockIdx.x] = s;
    }
}

// Each block redundantly scans the 147 block sums, then local scan + offset.
__global__ void scan3_kernel() {
    __shared__ int shB[256];
    __shared__ int shW[32];
    __shared__ int shO[32];
    __shared__ int s_bofs;
    const int tid  = threadIdx.x;
    const int lane = tid & 31;
    const int wid  = tid >> 5;

    if (tid < 256) shB[tid] = (tid < SCAN_NB) ? g_bsum[tid] : 0;
    __syncthreads();
    #pragma unroll
    for (int o = 1; o < 256; o <<= 1) {
        int v = (tid < 256 && tid >= o) ? shB[tid - o] : 0;
        __syncthreads();
        if (tid < 256) shB[tid] += v;
        __syncthreads();
    }
    if (tid == 0) s_bofs = (blockIdx.x > 0) ? shB[blockIdx.x - 1] : 0;
    __syncthreads();

    int i = blockIdx.x * SCAN_B + tid;
    int v = (i < NN) ? g_deg[i] : 0;
    int incl = warp_incl_scan(v);
    if (lane == 31) shW[wid] = incl;
    __syncthreads();
    if (wid == 0) {
        int t = (lane < SCAN_B / 32) ? shW[lane] : 0;
        shO[lane] = warp_incl_scan(t) - t;
    }
    __syncthreads();
    if (i < NN) {
        int excl = incl - v + shO[wid] + s_bofs;
        g_rowstart[i] = excl;
        g_fill[i]     = excl;
    }
    if (blockIdx.x == 0 && tid == 0) g_rowstart[NN] = NE;
}

__global__ void place_kernel(const int* __restrict__ ei) {
    int e = blockIdx.x * blockDim.x + threadIdx.x;
    if (e >= NE) return;
    int r = load_edge(ei, e);
    int c = load_edge(ei, NE + e);
    float n = g_dinv[r] * g_dinv[c];
    int idx = atomicAdd(&g_fill[r], 1);
    g_edge[idx] = make_int2(c, __float_as_int(n));
}

// ---------------- SpMM: 4 rows per warp, 16B lanes (LDG.128) -----------------
// Lane groups of 8 serve rows 4w..4w+3. Each lane owns dims [8*sub, 8*sub+8)
// as one uint4 (4x half2): one gather instruction covers 4 edges per warp.
// fp32 accumulation. MODE 0/1: xout = result (fp16).
// MODE 2: out = (x0 + x1 + x2 + result) * 0.25 in one pass.
template <int MODE>
__global__ void spmm4_kernel(const float* __restrict__ user,
                             const float* __restrict__ item,
                             const __half2* __restrict__ xin,
                             __half2* __restrict__ xout,
                             const __half2* __restrict__ xb1,
                             const __half2* __restrict__ xb2,
                             float* __restrict__ out) {
    int gw   = (blockIdx.x * blockDim.x + threadIdx.x) >> 5;  // warp -> 4 rows
    int lane = threadIdx.x & 31;
    if (4 * gw >= NN) return;
    int quarter = lane >> 3;
    int sub     = lane & 7;
    int row     = 4 * gw + quarter;

    int s = g_rowstart[row];
    int d = g_rowstart[row + 1] - s;
    int dm = max(d, __shfl_xor_sync(0xffffffffu, d, 8));
    dm = max(dm, __shfl_xor_sync(0xffffffffu, dm, 16));

    float a[8] = {0, 0, 0, 0, 0, 0, 0, 0};
    float b[8] = {0, 0, 0, 0, 0, 0, 0, 0};
    const char* xinb = reinterpret_cast<const char*>(xin);

    for (int i = 0; i < dm; i += 2) {
        if (i < d) {
            int2 e = __ldg(&g_edge[s + i]);
            uint4 v = __ldg(reinterpret_cast<const uint4*>(xinb + (size_t)e.x * 128) + sub);
            float f[8];  unpack8(v, f);
            float n = __int_as_float(e.y);
            #pragma unroll
            for (int k = 0; k < 8; k++) a[k] = fmaf(f[k], n, a[k]);
        }
        if (i + 1 < d) {
            int2 e = __ldg(&g_edge[s + i + 1]);
            uint4 v = __ldg(reinterpret_cast<const uint4*>(xinb + (size_t)e.x * 128) + sub);
            float f[8];  unpack8(v, f);
            float n = __int_as_float(e.y);
            #pragma unroll
            for (int k = 0; k < 8; k++) b[k] = fmaf(f[k], n, b[k]);
        }
    }
    #pragma unroll
    for (int k = 0; k < 8; k++) a[k] += b[k];

    if (MODE != 2) {
        __half2 h0 = __floats2half2_rn(a[0], a[1]);
        __half2 h1 = __floats2half2_rn(a[2], a[3]);
        __half2 h2 = __floats2half2_rn(a[4], a[5]);
        __half2 h3 = __floats2half2_rn(a[6], a[7]);
        uint4 w;
        w.x = *reinterpret_cast<unsigned int*>(&h0);
        w.y = *reinterpret_cast<unsigned int*>(&h1);
        w.z = *reinterpret_cast<unsigned int*>(&h2);
        w.w = *reinterpret_cast<unsigned int*>(&h3);
        *(reinterpret_cast<uint4*>(reinterpret_cast<char*>(xout) + (size_t)row * 128) + sub) = w;
    } else {
        size_t base = (size_t)row * DD + 8 * (size_t)sub;
        const float* xb = (row < NU) ? user + ((size_t)row * DD)
                                     : item + ((size_t)(row - NU) * DD);
        float4 x0a = __ldg(reinterpret_cast<const float4*>(xb) + 2 * sub);
        float4 x0b = __ldg(reinterpret_cast<const float4*>(xb) + 2 * sub + 1);
        uint4 u1 = __ldg(reinterpret_cast<const uint4*>(
                       reinterpret_cast<const char*>(xb1) + (size_t)row * 128) + sub);
        uint4 u2 = __ldg(reinterpret_cast<const uint4*>(
                       reinterpret_cast<const char*>(xb2) + (size_t)row * 128) + sub);
        float p[8], q[8];
        unpack8(u1, p);  unpack8(u2, q);
        float4 r0, r1;
        r0.x = (x0a.x + p[0] + q[0] + a[0]) * 0.25f;
        r0.y = (x0a.y + p[1] + q[1] + a[1]) * 0.25f;
        r0.z = (x0a.z + p[2] + q[2] + a[2]) * 0.25f;
        r0.w = (x0a.w + p[3] + q[3] + a[3]) * 0.25f;
        r1.x = (x0b.x + p[4] + q[4] + a[4]) * 0.25f;
        r1.y = (x0b.y + p[5] + q[5] + a[5]) * 0.25f;
        r1.z = (x0b.z + p[6] + q[6] + a[6]) * 0.25f;
        r1.w = (x0b.w + p[7] + q[7] + a[7]) * 0.25f;
        *reinterpret_cast<float4*>(out + base)     = r0;
        *reinterpret_cast<float4*>(out + base + 4) = r1;
    }
}

// ---------------- launch ------------------------------------------------------
extern "C" void kernel_launch(void* const* d_in, const int* in_sizes, int n_in,
                              void* d_out, int out_size) {
    const float* user = (const float*)d_in[0];
    const float* item = (const float*)d_in[1];
    const int*   ei   = (const int*)d_in[2];
    float* out = (float*)d_out;

    const int T = 256;
    zero_detect_convert_kernel<<<ZERO_BLKS + CONV_BLKS, T>>>(
        (const unsigned int*)ei, user, item);
    count_kernel<<<(NE + T - 1) / T, T>>>(ei);
    scan1_dinv_kernel<<<SCAN_NB, SCAN_B>>>();
    scan3_kernel<<<SCAN_NB, SCAN_B>>>();
    place_kernel<<<(NE + T - 1) / T, T>>>(ei);

    __half2* X0 = nullptr;
    cudaGetSymbolAddress((void**)&X0, g_Xh);
    __half2* X1 = X0 + FEATH;
    __half2* X2 = X1 + FEATH;

    const int warps = NN / 4;                          // 4 rows per warp
    const int spmm_blocks = (warps * 32 + T - 1) / T;  // 4688
    spmm4_kernel<0><<<spmm_blocks, T>>>(user, item, X0, X1, nullptr, nullptr, out);
    spmm4_kernel<1><<<spmm_blocks, T>>>(user, item, X1, X2, nullptr, nullptr, out);
    spmm4_kernel<2><<<spmm_blocks, T>>>(user, item, X2, nullptr, X1, X2, out);
}